// round 15
// baseline (speedup 1.0000x reference)
#include <cuda_runtime.h>
#include <cuda_fp16.h>
#include <math.h>

// Problem constants
#define BATCH 4
#define SEQ   2048
#define CDIM  1024
#define NH    16
#define HD    64
#define ROWS  (BATCH*SEQ)      // 8192
#define QKVC  (3*CDIM)         // 3072

// Scratch (allocation-free rule: __device__ globals)
__device__ __half g_qkvh[(size_t)ROWS * 2 * CDIM];     // Q|K rows, half
__device__ __half g_vT[(size_t)BATCH * NH * HD * SEQ]; // V transposed [b][h][d][t]
__device__ __half g_xh[(size_t)ROWS * CDIM];           // x as half
__device__ __half g_waT[(size_t)QKVC * CDIM];          // W_attn^T [N][K]
__device__ __half g_wpT[(size_t)CDIM * CDIM];          // W_proj^T [N][K]
__device__ __half g_yh[(size_t)ROWS * CDIM];           // attn out, half

__device__ __forceinline__ void mma_f16(float c[4], unsigned a0, unsigned a1,
                                        unsigned a2, unsigned a3,
                                        unsigned b0, unsigned b1) {
    asm volatile(
        "mma.sync.aligned.m16n8k16.row.col.f32.f16.f16.f32 "
        "{%0,%1,%2,%3}, {%4,%5,%6,%7}, {%8,%9}, {%0,%1,%2,%3};\n"
        : "+f"(c[0]), "+f"(c[1]), "+f"(c[2]), "+f"(c[3])
        : "r"(a0), "r"(a1), "r"(a2), "r"(a3), "r"(b0), "r"(b1));
}
__device__ __forceinline__ void ldsm4(unsigned& r0, unsigned& r1, unsigned& r2,
                                      unsigned& r3, unsigned addr) {
    asm volatile("ldmatrix.sync.aligned.m8n8.x4.shared.b16 {%0,%1,%2,%3}, [%4];"
                 : "=r"(r0), "=r"(r1), "=r"(r2), "=r"(r3) : "r"(addr));
}
__device__ __forceinline__ void cp16(unsigned smem_addr, const void* gptr) {
    asm volatile("cp.async.cg.shared.global [%0], [%1], 16;\n"
                 :: "r"(smem_addr), "l"(gptr));
}
__device__ __forceinline__ void cp_commit() {
    asm volatile("cp.async.commit_group;\n" ::);
}
__device__ __forceinline__ unsigned h2u(__half2 h) { return *(unsigned*)&h; }
__device__ __forceinline__ unsigned hmul2u(unsigned a, unsigned s) {
    __half2 r = __hmul2(*(__half2*)&a, *(__half2*)&s);
    return *(unsigned*)&r;
}

// ---------------------------------------------------------------------------
// Pre-pass 1: fp32 -> half, contiguous.
// ---------------------------------------------------------------------------
__global__ __launch_bounds__(256)
void conv_half(const float* __restrict__ in, __half* __restrict__ out, int n4)
{
    int i = blockIdx.x * blockDim.x + threadIdx.x;
    if (i < n4) {
        float4 v = ((const float4*)in)[i];
        __half2 lo = __floats2half2_rn(v.x, v.y);
        __half2 hi = __floats2half2_rn(v.z, v.w);
        ((uint2*)out)[i] = make_uint2(h2u(lo), h2u(hi));
    }
}

// ---------------------------------------------------------------------------
// Pre-pass 2: transpose + convert. in [K][N] f32 -> out [N][K] half.
// ---------------------------------------------------------------------------
__global__ __launch_bounds__(256)
void transpose_h(const float* __restrict__ in, __half* __restrict__ out,
                 int K, int N)
{
    __shared__ float t[32][33];
    const int n0 = blockIdx.x * 32, k0 = blockIdx.y * 32;
    const int tx = threadIdx.x, ty = threadIdx.y;
#pragma unroll
    for (int i = 0; i < 4; i++)
        t[ty + 8 * i][tx] = in[(size_t)(k0 + ty + 8 * i) * N + n0 + tx];
    __syncthreads();
#pragma unroll
    for (int i = 0; i < 4; i++)
        out[(size_t)(n0 + ty + 8 * i) * K + k0 + tx] =
            __float2half_rn(t[tx][ty + 8 * i]);
}

// ---------------------------------------------------------------------------
// fp16 tensor-core GEMM + bias. A [M][K] half, Bt [N][K] half (both K-major).
// Block 128x128xBK64, 256 thr = 8 warps (2x4), warp 64x32.
// ldmatrix.x4 fragment loads, DOUBLE-BUFFERED in registers: kb+1's ldsm
// issue before kb's mma consume -> ldsm latency hidden behind HMMA stream.
// 3-stage cp.async, one __syncthreads per 64-wide k-tile.
// ---------------------------------------------------------------------------
#define BK 64
#define AH_STRIDE 36                 // u32 per row: 32 data + 4 pad
#define AH_SZ (128 * AH_STRIDE)      // u32 units per stage per operand
#define GEMM_SMEM_H (3 * 2 * AH_SZ * 4)   // 110592 B

__global__ __launch_bounds__(256, 2)
void gemm_h(const __half* __restrict__ A, const __half* __restrict__ Bt,
            const float* __restrict__ bias, float* __restrict__ Cf,
            __half* __restrict__ qkvh, __half* __restrict__ vT,
            int M, int N, int K, int mode)
{
    extern __shared__ unsigned smh[];
    unsigned* Asm = smh;                 // [3][AH_SZ]
    unsigned* Bsm = smh + 3 * AH_SZ;     // [3][AH_SZ]

    const int tid   = threadIdx.x;
    const int wid   = tid >> 5;
    const int lane  = tid & 31;
    const int warpM = wid >> 2;          // 0..1
    const int warpN = wid & 3;           // 0..3
    const int g     = lane >> 2;
    const int t     = lane & 3;

    const int rowBase = blockIdx.y * 128;
    const int colBase = blockIdx.x * 128;

    const unsigned sAb = (unsigned)__cvta_generic_to_shared(Asm);
    const unsigned sBb = (unsigned)__cvta_generic_to_shared(Bsm);

    // ldmatrix lane roles
    const int m  = lane >> 3;            // matrix 0..3
    const int mr = lane & 7;
    const int aRowF = warpM * 64 + (m & 1) * 8 + mr;   // + mt*16
    const int aKsel = (m >> 1) * 4;
    const int bColF = warpN * 32 + (m >> 1) * 8 + mr;  // + ntp*16
    const int bKsel = (m & 1) * 4;

    float acc[4][4][4];
#pragma unroll
    for (int mt = 0; mt < 4; mt++)
#pragma unroll
        for (int nt = 0; nt < 4; nt++)
#pragma unroll
            for (int i = 0; i < 4; i++) acc[mt][nt][i] = 0.f;

    const int nTiles = K / BK;

    auto loadTile = [&](int s, int k0) {
#pragma unroll
        for (int i = 0; i < 4; i++) {
            int idx = tid + i * 256;          // 0..1023
            int row = idx >> 3, c8 = idx & 7; // 128 rows x 8 chunks
            cp16(sAb + (s * AH_SZ + row * AH_STRIDE + 4 * c8) * 4,
                 A + (size_t)(rowBase + row) * K + k0 + 8 * c8);
            cp16(sBb + (s * AH_SZ + row * AH_STRIDE + 4 * c8) * 4,
                 Bt + (size_t)(colBase + row) * K + k0 + 8 * c8);
        }
    };

    loadTile(0, 0);   cp_commit();
    loadTile(1, BK);  cp_commit();

    // fragment double buffers
    unsigned af[2][4][4];
    unsigned bf[2][4][2];

    for (int kt = 0; kt < nTiles; kt++) {
        asm volatile("cp.async.wait_group 1;\n" ::);
        __syncthreads();
        if (kt + 2 < nTiles) loadTile((kt + 2) % 3, (kt + 2) * BK);
        cp_commit();

        const unsigned aBase = sAb + ((kt % 3) * AH_SZ) * 4;
        const unsigned bBase = sBb + ((kt % 3) * AH_SZ) * 4;

        // prologue: fragments for kb=0 into buffer 0
#pragma unroll
        for (int mt = 0; mt < 4; mt++)
            ldsm4(af[0][mt][0], af[0][mt][1], af[0][mt][2], af[0][mt][3],
                  aBase + ((aRowF + mt * 16) * AH_STRIDE + aKsel) * 4);
        ldsm4(bf[0][0][0], bf[0][0][1], bf[0][1][0], bf[0][1][1],
              bBase + ((bColF +  0) * AH_STRIDE + bKsel) * 4);
        ldsm4(bf[0][2][0], bf[0][2][1], bf[0][3][0], bf[0][3][1],
              bBase + ((bColF + 16) * AH_STRIDE + bKsel) * 4);

#pragma unroll
        for (int kb = 0; kb < 4; kb++) {
            const int cur = kb & 1, nxt = cur ^ 1;
            if (kb < 3) {   // issue kb+1 ldsm BEFORE consuming kb
#pragma unroll
                for (int mt = 0; mt < 4; mt++)
                    ldsm4(af[nxt][mt][0], af[nxt][mt][1], af[nxt][mt][2],
                          af[nxt][mt][3],
                          aBase + ((aRowF + mt * 16) * AH_STRIDE
                                   + (kb + 1) * 8 + aKsel) * 4);
                ldsm4(bf[nxt][0][0], bf[nxt][0][1], bf[nxt][1][0], bf[nxt][1][1],
                      bBase + ((bColF +  0) * AH_STRIDE + (kb + 1) * 8 + bKsel) * 4);
                ldsm4(bf[nxt][2][0], bf[nxt][2][1], bf[nxt][3][0], bf[nxt][3][1],
                      bBase + ((bColF + 16) * AH_STRIDE + (kb + 1) * 8 + bKsel) * 4);
            }
#pragma unroll
            for (int mt = 0; mt < 4; mt++)
#pragma unroll
                for (int nt = 0; nt < 4; nt++)
                    mma_f16(acc[mt][nt], af[cur][mt][0], af[cur][mt][1],
                            af[cur][mt][2], af[cur][mt][3],
                            bf[cur][nt][0], bf[cur][nt][1]);
        }
    }

#pragma unroll
    for (int mt = 0; mt < 4; mt++) {
        int r0 = rowBase + warpM * 64 + mt * 16 + g;
#pragma unroll
        for (int nt = 0; nt < 4; nt++) {
            int c = colBase + warpN * 32 + nt * 8 + 2 * t;
            float b0 = bias[c], b1 = bias[c + 1];
            float o00 = acc[mt][nt][0] + b0, o01 = acc[mt][nt][1] + b1;
            float o10 = acc[mt][nt][2] + b0, o11 = acc[mt][nt][3] + b1;
            if (mode == 0) {
                *(float2*)&Cf[(size_t)(r0 + 0) * N + c] = make_float2(o00, o01);
                *(float2*)&Cf[(size_t)(r0 + 8) * N + c] = make_float2(o10, o11);
            } else if (c < 2 * CDIM) {
                *(unsigned*)&qkvh[(size_t)(r0 + 0) * 2048 + c] =
                    h2u(__floats2half2_rn(o00, o01));
                *(unsigned*)&qkvh[(size_t)(r0 + 8) * 2048 + c] =
                    h2u(__floats2half2_rn(o10, o11));
            } else {
                int hh = (c - 2 * CDIM) >> 6, d = (c - 2 * CDIM) & 63;
                int bb = r0 >> 11, tt = r0 & 2047;
                size_t rb = ((size_t)bb * NH + hh) * HD;
                vT[(rb + d    ) * SEQ + tt    ] = __float2half_rn(o00);
                vT[(rb + d + 1) * SEQ + tt    ] = __float2half_rn(o01);
                vT[(rb + d    ) * SEQ + tt + 8] = __float2half_rn(o10);
                vT[(rb + d + 1) * SEQ + tt + 8] = __float2half_rn(o11);
            }
        }
    }
}

// ---------------------------------------------------------------------------
// fp16 tensor-core flash attention (unchanged from R13 pass).
// ---------------------------------------------------------------------------
#define BQ 128
#define BKV 64
#define TS_H 36
#define KV_SZ (BKV * TS_H)
#define ATTN_SMEM_H ((3 * KV_SZ + 3 * KV_SZ + BQ * TS_H) * 4)   // 73728 B

__global__ __launch_bounds__(256)
void attn_h(const __half* __restrict__ qkvh, const __half* __restrict__ vT,
            __half* __restrict__ yh)
{
    extern __shared__ unsigned smem[];
    unsigned* Ks = smem;                    // [3][KV_SZ]
    unsigned* Vs = smem + 3 * KV_SZ;        // [3][KV_SZ]
    unsigned* Ps = Vs + 3 * KV_SZ;          // [BQ][TS_H]

    const int q0 = blockIdx.x * BQ;
    const int h  = blockIdx.y;
    const int b  = blockIdx.z;

    const int tid  = threadIdx.x;
    const int w    = tid >> 5;
    const int lane = tid & 31;
    const int g    = lane >> 2;
    const int t    = lane & 3;

    const int rowA = q0 + w * 16 + g;
    const size_t vbase = ((size_t)b * NH + h) * HD;

    const unsigned ksb = (unsigned)__cvta_generic_to_shared(Ks);
    const unsigned vsb = (unsigned)__cvta_generic_to_shared(Vs);
    const unsigned psb = (unsigned)__cvta_generic_to_shared(Ps);

    const int m  = lane >> 3;
    const int mr = lane & 7;
    const int nRowF = (m >> 1) * 8 + mr;
    const int nKsel = (m & 1) * 4;
    const int pRowF = w * 16 + (m & 1) * 8 + mr;
    const int pKsel = (m >> 1) * 4;

    auto loadKV = [&](int s, int k0) {
#pragma unroll
        for (int i = 0; i < 2; i++) {
            int idx = tid + i * 256;
            int row = idx >> 3, c8 = idx & 7;
            cp16(ksb + (s * KV_SZ + row * TS_H + 4 * c8) * 4,
                 qkvh + (size_t)(b * SEQ + k0 + row) * 2048 + CDIM + h * HD + 8 * c8);
            cp16(vsb + (s * KV_SZ + row * TS_H + 4 * c8) * 4,
                 vT + (vbase + row) * SEQ + k0 + 8 * c8);
        }
    };

    // Q fragments, scaled by 0.125 (power of 2: exact)
    unsigned qa[4][4];
    {
        const unsigned* Q0 = (const unsigned*)(qkvh + (size_t)(b * SEQ + rowA) * 2048 + h * HD);
        const unsigned* Q8 = Q0 + 8 * 1024;
        const unsigned sc = h2u(__float2half2_rn(0.125f));
#pragma unroll
        for (int kb = 0; kb < 4; kb++) {
            qa[kb][0] = hmul2u(Q0[kb * 8 + t], sc);
            qa[kb][1] = hmul2u(Q8[kb * 8 + t], sc);
            qa[kb][2] = hmul2u(Q0[kb * 8 + t + 4], sc);
            qa[kb][3] = hmul2u(Q8[kb * 8 + t + 4], sc);
        }
    }

    float O[8][4];
#pragma unroll
    for (int nt = 0; nt < 8; nt++)
#pragma unroll
        for (int i = 0; i < 4; i++) O[nt][i] = 0.f;
    float m0 = -INFINITY, m1 = -INFINITY, l0 = 0.f, l1 = 0.f;

    const int ntiles = (q0 + BQ) >> 6;     // >= 2 always

    loadKV(0, 0);  cp_commit();
    loadKV(1, 64); cp_commit();

    for (int kt = 0; kt < ntiles; kt++) {
        const int k0 = kt << 6;
        asm volatile("cp.async.wait_group 1;\n" ::);   // tile kt resident
        __syncthreads();
        if (kt + 2 < ntiles) loadKV((kt + 2) % 3, (kt + 2) << 6);
        cp_commit();

        if (k0 > q0 + w * 16 + 15) continue;   // exact identity update -> skip

        const unsigned ksB = ksb + ((kt % 3) * KV_SZ) * 4;
        const unsigned vsB = vsb + ((kt % 3) * KV_SZ) * 4;

        float S[8][4];
#pragma unroll
        for (int nt = 0; nt < 8; nt++)
#pragma unroll
            for (int i = 0; i < 4; i++) S[nt][i] = 0.f;

#pragma unroll
        for (int kb = 0; kb < 4; kb++) {
            unsigned kf[8][2];
#pragma unroll
            for (int ntp = 0; ntp < 4; ntp++)
                ldsm4(kf[2*ntp][0], kf[2*ntp][1], kf[2*ntp+1][0], kf[2*ntp+1][1],
                      ksB + ((ntp * 16 + nRowF) * TS_H + kb * 8 + nKsel) * 4);
#pragma unroll
            for (int nt = 0; nt < 8; nt++)
                mma_f16(S[nt], qa[kb][0], qa[kb][1], qa[kb][2], qa[kb][3],
                        kf[nt][0], kf[nt][1]);
        }

        if (k0 + BKV - 1 > q0 + w * 16) {
#pragma unroll
            for (int nt = 0; nt < 8; nt++) {
                int col = k0 + nt * 8 + 2 * t;
                if (col > rowA)         S[nt][0] = -INFINITY;
                if (col + 1 > rowA)     S[nt][1] = -INFINITY;
                if (col > rowA + 8)     S[nt][2] = -INFINITY;
                if (col + 1 > rowA + 8) S[nt][3] = -INFINITY;
            }
        }

        float mt0 = -INFINITY, mt1 = -INFINITY;
#pragma unroll
        for (int nt = 0; nt < 8; nt++) {
            mt0 = fmaxf(mt0, fmaxf(S[nt][0], S[nt][1]));
            mt1 = fmaxf(mt1, fmaxf(S[nt][2], S[nt][3]));
        }
#pragma unroll
        for (int off = 1; off < 4; off <<= 1) {
            mt0 = fmaxf(mt0, __shfl_xor_sync(0xffffffffu, mt0, off));
            mt1 = fmaxf(mt1, __shfl_xor_sync(0xffffffffu, mt1, off));
        }
        float mn0 = fmaxf(m0, mt0), mn1 = fmaxf(m1, mt1);
        float al0 = __expf(m0 - mn0), al1 = __expf(m1 - mn1);
        m0 = mn0; m1 = mn1;

        float ls0 = 0.f, ls1 = 0.f;
        unsigned* p0 = &Ps[(w * 16 + g) * TS_H];
        unsigned* p1 = p0 + 8 * TS_H;
#pragma unroll
        for (int nt = 0; nt < 8; nt++) {
            float e00 = __expf(S[nt][0] - mn0);
            float e01 = __expf(S[nt][1] - mn0);
            float e10 = __expf(S[nt][2] - mn1);
            float e11 = __expf(S[nt][3] - mn1);
            ls0 += e00 + e01;
            ls1 += e10 + e11;
            p0[nt * 4 + t] = h2u(__floats2half2_rn(e00, e01));
            p1[nt * 4 + t] = h2u(__floats2half2_rn(e10, e11));
        }
#pragma unroll
        for (int off = 1; off < 4; off <<= 1) {
            ls0 += __shfl_xor_sync(0xffffffffu, ls0, off);
            ls1 += __shfl_xor_sync(0xffffffffu, ls1, off);
        }
        l0 = l0 * al0 + ls0;
        l1 = l1 * al1 + ls1;
#pragma unroll
        for (int nt = 0; nt < 8; nt++) {
            O[nt][0] *= al0; O[nt][1] *= al0;
            O[nt][2] *= al1; O[nt][3] *= al1;
        }
        __syncwarp();

#pragma unroll
        for (int kbv = 0; kbv < 4; kbv++) {
            unsigned pa[4];
            ldsm4(pa[0], pa[1], pa[2], pa[3],
                  psb + (pRowF * TS_H + kbv * 8 + pKsel) * 4);
            unsigned vf[8][2];
#pragma unroll
            for (int ntp = 0; ntp < 4; ntp++)
                ldsm4(vf[2*ntp][0], vf[2*ntp][1], vf[2*ntp+1][0], vf[2*ntp+1][1],
                      vsB + ((ntp * 16 + nRowF) * TS_H + kbv * 8 + nKsel) * 4);
#pragma unroll
            for (int nt = 0; nt < 8; nt++)
                mma_f16(O[nt], pa[0], pa[1], pa[2], pa[3],
                        vf[nt][0], vf[nt][1]);
        }
    }

    float inv0 = 1.f / l0, inv1 = 1.f / l1;
    __half* y0 = yh + (size_t)(b * SEQ + rowA) * CDIM + h * HD;
    __half* y1 = y0 + (size_t)8 * CDIM;
#pragma unroll
    for (int nt = 0; nt < 8; nt++) {
        *(unsigned*)&y0[nt * 8 + 2 * t] =
            h2u(__floats2half2_rn(O[nt][0] * inv0, O[nt][1] * inv0));
        *(unsigned*)&y1[nt * 8 + 2 * t] =
            h2u(__floats2half2_rn(O[nt][2] * inv1, O[nt][3] * inv1));
    }
}

// ---------------------------------------------------------------------------
extern "C" void kernel_launch(void* const* d_in, const int* in_sizes, int n_in,
                              void* d_out, int out_size)
{
    const float* x      = (const float*)d_in[0];
    const float* W_attn = (const float*)d_in[1];
    const float* b_attn = (const float*)d_in[2];
    const float* W_proj = (const float*)d_in[3];
    const float* b_proj = (const float*)d_in[4];
    float* out = (float*)d_out;

    __half *qkvh, *vT, *xh, *waT, *wpT, *yh;
    cudaGetSymbolAddress((void**)&qkvh, g_qkvh);
    cudaGetSymbolAddress((void**)&vT,   g_vT);
    cudaGetSymbolAddress((void**)&xh,   g_xh);
    cudaGetSymbolAddress((void**)&waT,  g_waT);
    cudaGetSymbolAddress((void**)&wpT,  g_wpT);
    cudaGetSymbolAddress((void**)&yh,   g_yh);

    cudaFuncSetAttribute(gemm_h, cudaFuncAttributeMaxDynamicSharedMemorySize,
                         GEMM_SMEM_H);
    cudaFuncSetAttribute(attn_h, cudaFuncAttributeMaxDynamicSharedMemorySize,
                         ATTN_SMEM_H);

    // 0) pre-pass
    {
        int n4x = ROWS * CDIM / 4;
        conv_half<<<(n4x + 255) / 256, 256>>>(x, xh, n4x);
        transpose_h<<<dim3(QKVC / 32, CDIM / 32), dim3(32, 8)>>>(W_attn, waT,
                                                                 CDIM, QKVC);
        transpose_h<<<dim3(CDIM / 32, CDIM / 32), dim3(32, 8)>>>(W_proj, wpT,
                                                                 CDIM, CDIM);
    }

    // 1) qkv = xh @ waT^T + b_attn -> Q|K rows (half) + V transposed (half)
    gemm_h<<<dim3(QKVC / 128, ROWS / 128), 256, GEMM_SMEM_H>>>(
        xh, waT, b_attn, nullptr, qkvh, vT, ROWS, QKVC, CDIM, 1);
    // 2) attention -> yh (half)
    attn_h<<<dim3(SEQ / BQ, NH, BATCH), 256, ATTN_SMEM_H>>>(qkvh, vT, yh);
    // 3) out = yh @ wpT^T + b_proj (fp32 out)
    gemm_h<<<dim3(CDIM / 128, ROWS / 128), 256, GEMM_SMEM_H>>>(
        yh, wpT, b_proj, out, nullptr, nullptr, ROWS, CDIM, CDIM, 0);
}

// round 16
// speedup vs baseline: 1.0471x; 1.0471x over previous
#include <cuda_runtime.h>
#include <cuda_fp16.h>
#include <math.h>

// Problem constants
#define BATCH 4
#define SEQ   2048
#define CDIM  1024
#define NH    16
#define HD    64
#define ROWS  (BATCH*SEQ)      // 8192
#define QKVC  (3*CDIM)         // 3072

// Scratch (allocation-free rule: __device__ globals)
__device__ __half g_qkvh[(size_t)ROWS * 2 * CDIM];     // Q|K rows, half
__device__ __half g_vT[(size_t)BATCH * NH * HD * SEQ]; // V transposed [b][h][d][t]
__device__ __half g_xh[(size_t)ROWS * CDIM];           // x as half
__device__ __half g_waT[(size_t)QKVC * CDIM];          // W_attn^T [N][K]
__device__ __half g_wpT[(size_t)CDIM * CDIM];          // W_proj^T [N][K]
__device__ __half g_yh[(size_t)ROWS * CDIM];           // attn out, half

__device__ __forceinline__ void mma_f16(float c[4], unsigned a0, unsigned a1,
                                        unsigned a2, unsigned a3,
                                        unsigned b0, unsigned b1) {
    asm volatile(
        "mma.sync.aligned.m16n8k16.row.col.f32.f16.f16.f32 "
        "{%0,%1,%2,%3}, {%4,%5,%6,%7}, {%8,%9}, {%0,%1,%2,%3};\n"
        : "+f"(c[0]), "+f"(c[1]), "+f"(c[2]), "+f"(c[3])
        : "r"(a0), "r"(a1), "r"(a2), "r"(a3), "r"(b0), "r"(b1));
}
__device__ __forceinline__ void ldsm4(unsigned& r0, unsigned& r1, unsigned& r2,
                                      unsigned& r3, unsigned addr) {
    asm volatile("ldmatrix.sync.aligned.m8n8.x4.shared.b16 {%0,%1,%2,%3}, [%4];"
                 : "=r"(r0), "=r"(r1), "=r"(r2), "=r"(r3) : "r"(addr));
}
__device__ __forceinline__ void cp16(unsigned smem_addr, const void* gptr) {
    asm volatile("cp.async.cg.shared.global [%0], [%1], 16;\n"
                 :: "r"(smem_addr), "l"(gptr));
}
__device__ __forceinline__ void cp_commit() {
    asm volatile("cp.async.commit_group;\n" ::);
}
__device__ __forceinline__ unsigned h2u(__half2 h) { return *(unsigned*)&h; }
__device__ __forceinline__ unsigned hmul2u(unsigned a, unsigned s) {
    __half2 r = __hmul2(*(__half2*)&a, *(__half2*)&s);
    return *(unsigned*)&r;
}

// ---------------------------------------------------------------------------
// Pre-pass 1: fp32 -> half, contiguous.
// ---------------------------------------------------------------------------
__global__ __launch_bounds__(256)
void conv_half(const float* __restrict__ in, __half* __restrict__ out, int n4)
{
    int i = blockIdx.x * blockDim.x + threadIdx.x;
    if (i < n4) {
        float4 v = ((const float4*)in)[i];
        __half2 lo = __floats2half2_rn(v.x, v.y);
        __half2 hi = __floats2half2_rn(v.z, v.w);
        ((uint2*)out)[i] = make_uint2(h2u(lo), h2u(hi));
    }
}

// ---------------------------------------------------------------------------
// Pre-pass 2: transpose + convert. in [K][N] f32 -> out [N][K] half.
// ---------------------------------------------------------------------------
__global__ __launch_bounds__(256)
void transpose_h(const float* __restrict__ in, __half* __restrict__ out,
                 int K, int N)
{
    __shared__ float t[32][33];
    const int n0 = blockIdx.x * 32, k0 = blockIdx.y * 32;
    const int tx = threadIdx.x, ty = threadIdx.y;
#pragma unroll
    for (int i = 0; i < 4; i++)
        t[ty + 8 * i][tx] = in[(size_t)(k0 + ty + 8 * i) * N + n0 + tx];
    __syncthreads();
#pragma unroll
    for (int i = 0; i < 4; i++)
        out[(size_t)(n0 + ty + 8 * i) * K + k0 + tx] =
            __float2half_rn(t[tx][ty + 8 * i]);
}

// ---------------------------------------------------------------------------
// fp16 tensor-core GEMM + bias (R13 version, best measured: 160.7us on qkv).
// A [M][K] half, Bt [N][K] half. Block 128x128xBK64, 8 warps, warp 64x32.
// ---------------------------------------------------------------------------
#define BK 64
#define AH_STRIDE 36                 // u32 per row: 32 data + 4 pad
#define AH_SZ (128 * AH_STRIDE)
#define GEMM_SMEM_H (3 * 2 * AH_SZ * 4)   // 110592 B

__global__ __launch_bounds__(256, 2)
void gemm_h(const __half* __restrict__ A, const __half* __restrict__ Bt,
            const float* __restrict__ bias, float* __restrict__ Cf,
            __half* __restrict__ qkvh, __half* __restrict__ vT,
            int M, int N, int K, int mode)
{
    extern __shared__ unsigned smh[];
    unsigned* Asm = smh;                 // [3][AH_SZ]
    unsigned* Bsm = smh + 3 * AH_SZ;     // [3][AH_SZ]

    const int tid   = threadIdx.x;
    const int wid   = tid >> 5;
    const int lane  = tid & 31;
    const int warpM = wid >> 2;
    const int warpN = wid & 3;
    const int g     = lane >> 2;
    const int t     = lane & 3;

    const int rowBase = blockIdx.y * 128;
    const int colBase = blockIdx.x * 128;

    const unsigned sAb = (unsigned)__cvta_generic_to_shared(Asm);
    const unsigned sBb = (unsigned)__cvta_generic_to_shared(Bsm);

    const int m  = lane >> 3;
    const int mr = lane & 7;
    const int aRowF = warpM * 64 + (m & 1) * 8 + mr;
    const int aKsel = (m >> 1) * 4;
    const int bColF = warpN * 32 + (m >> 1) * 8 + mr;
    const int bKsel = (m & 1) * 4;

    float acc[4][4][4];
#pragma unroll
    for (int mt = 0; mt < 4; mt++)
#pragma unroll
        for (int nt = 0; nt < 4; nt++)
#pragma unroll
            for (int i = 0; i < 4; i++) acc[mt][nt][i] = 0.f;

    const int nTiles = K / BK;

    auto loadTile = [&](int s, int k0) {
#pragma unroll
        for (int i = 0; i < 4; i++) {
            int idx = tid + i * 256;
            int row = idx >> 3, c8 = idx & 7;
            cp16(sAb + (s * AH_SZ + row * AH_STRIDE + 4 * c8) * 4,
                 A + (size_t)(rowBase + row) * K + k0 + 8 * c8);
            cp16(sBb + (s * AH_SZ + row * AH_STRIDE + 4 * c8) * 4,
                 Bt + (size_t)(colBase + row) * K + k0 + 8 * c8);
        }
    };

    loadTile(0, 0);   cp_commit();
    loadTile(1, BK);  cp_commit();

    for (int kt = 0; kt < nTiles; kt++) {
        asm volatile("cp.async.wait_group 1;\n" ::);
        __syncthreads();
        if (kt + 2 < nTiles) loadTile((kt + 2) % 3, (kt + 2) * BK);
        cp_commit();

        const unsigned aBase = sAb + ((kt % 3) * AH_SZ) * 4;
        const unsigned bBase = sBb + ((kt % 3) * AH_SZ) * 4;

#pragma unroll
        for (int kb = 0; kb < 4; kb++) {
            unsigned af[4][4];
#pragma unroll
            for (int mt = 0; mt < 4; mt++)
                ldsm4(af[mt][0], af[mt][1], af[mt][2], af[mt][3],
                      aBase + ((aRowF + mt * 16) * AH_STRIDE + kb * 8 + aKsel) * 4);
            unsigned bf[4][2];
            ldsm4(bf[0][0], bf[0][1], bf[1][0], bf[1][1],
                  bBase + ((bColF +  0) * AH_STRIDE + kb * 8 + bKsel) * 4);
            ldsm4(bf[2][0], bf[2][1], bf[3][0], bf[3][1],
                  bBase + ((bColF + 16) * AH_STRIDE + kb * 8 + bKsel) * 4);
#pragma unroll
            for (int mt = 0; mt < 4; mt++)
#pragma unroll
                for (int nt = 0; nt < 4; nt++)
                    mma_f16(acc[mt][nt], af[mt][0], af[mt][1], af[mt][2],
                            af[mt][3], bf[nt][0], bf[nt][1]);
        }
    }

#pragma unroll
    for (int mt = 0; mt < 4; mt++) {
        int r0 = rowBase + warpM * 64 + mt * 16 + g;
#pragma unroll
        for (int nt = 0; nt < 4; nt++) {
            int c = colBase + warpN * 32 + nt * 8 + 2 * t;
            float b0 = bias[c], b1 = bias[c + 1];
            float o00 = acc[mt][nt][0] + b0, o01 = acc[mt][nt][1] + b1;
            float o10 = acc[mt][nt][2] + b0, o11 = acc[mt][nt][3] + b1;
            if (mode == 0) {
                *(float2*)&Cf[(size_t)(r0 + 0) * N + c] = make_float2(o00, o01);
                *(float2*)&Cf[(size_t)(r0 + 8) * N + c] = make_float2(o10, o11);
            } else if (c < 2 * CDIM) {
                *(unsigned*)&qkvh[(size_t)(r0 + 0) * 2048 + c] =
                    h2u(__floats2half2_rn(o00, o01));
                *(unsigned*)&qkvh[(size_t)(r0 + 8) * 2048 + c] =
                    h2u(__floats2half2_rn(o10, o11));
            } else {
                int hh = (c - 2 * CDIM) >> 6, d = (c - 2 * CDIM) & 63;
                int bb = r0 >> 11, tt = r0 & 2047;
                size_t rb = ((size_t)bb * NH + hh) * HD;
                vT[(rb + d    ) * SEQ + tt    ] = __float2half_rn(o00);
                vT[(rb + d + 1) * SEQ + tt    ] = __float2half_rn(o01);
                vT[(rb + d    ) * SEQ + tt + 8] = __float2half_rn(o10);
                vT[(rb + d + 1) * SEQ + tt + 8] = __float2half_rn(o11);
            }
        }
    }
}

// ---------------------------------------------------------------------------
// fp16 tensor-core flash attention. KEY CHANGE: P stays in REGISTERS.
// The m16n8k16 accumulator layout (thread(g,t): rows g,g+8 x cols 2t,2t+1)
// IS the A-operand fragment layout for the PV mma:
//   pa0 = half2(e00,e01)[nt=2kbv], pa1 = half2(e10,e11)[nt=2kbv],
//   pa2 = half2(e00,e01)[nt=2kbv+1], pa3 = half2(e10,e11)[nt=2kbv+1].
// Eliminates the Ps smem round-trip (16 STS + 4 ldsm4 + syncwarp per tile).
// 3-stage cp.async KV pipeline (prefetch distance 2).
// ---------------------------------------------------------------------------
#define BQ 128
#define BKV 64
#define TS_H 36
#define KV_SZ (BKV * TS_H)
#define ATTN_SMEM_H ((3 * KV_SZ + 3 * KV_SZ) * 4)   // 55296 B

__global__ __launch_bounds__(256)
void attn_h(const __half* __restrict__ qkvh, const __half* __restrict__ vT,
            __half* __restrict__ yh)
{
    extern __shared__ unsigned smem[];
    unsigned* Ks = smem;                    // [3][KV_SZ]
    unsigned* Vs = smem + 3 * KV_SZ;        // [3][KV_SZ]

    const int q0 = blockIdx.x * BQ;
    const int h  = blockIdx.y;
    const int b  = blockIdx.z;

    const int tid  = threadIdx.x;
    const int w    = tid >> 5;
    const int lane = tid & 31;
    const int g    = lane >> 2;
    const int t    = lane & 3;

    const int rowA = q0 + w * 16 + g;
    const size_t vbase = ((size_t)b * NH + h) * HD;

    const unsigned ksb = (unsigned)__cvta_generic_to_shared(Ks);
    const unsigned vsb = (unsigned)__cvta_generic_to_shared(Vs);

    const int m  = lane >> 3;
    const int mr = lane & 7;
    const int nRowF = (m >> 1) * 8 + mr;
    const int nKsel = (m & 1) * 4;

    auto loadKV = [&](int s, int k0) {
#pragma unroll
        for (int i = 0; i < 2; i++) {
            int idx = tid + i * 256;
            int row = idx >> 3, c8 = idx & 7;
            cp16(ksb + (s * KV_SZ + row * TS_H + 4 * c8) * 4,
                 qkvh + (size_t)(b * SEQ + k0 + row) * 2048 + CDIM + h * HD + 8 * c8);
            cp16(vsb + (s * KV_SZ + row * TS_H + 4 * c8) * 4,
                 vT + (vbase + row) * SEQ + k0 + 8 * c8);
        }
    };

    // Q fragments, scaled by 0.125 (power of 2: exact)
    unsigned qa[4][4];
    {
        const unsigned* Q0 = (const unsigned*)(qkvh + (size_t)(b * SEQ + rowA) * 2048 + h * HD);
        const unsigned* Q8 = Q0 + 8 * 1024;
        const unsigned sc = h2u(__float2half2_rn(0.125f));
#pragma unroll
        for (int kb = 0; kb < 4; kb++) {
            qa[kb][0] = hmul2u(Q0[kb * 8 + t], sc);
            qa[kb][1] = hmul2u(Q8[kb * 8 + t], sc);
            qa[kb][2] = hmul2u(Q0[kb * 8 + t + 4], sc);
            qa[kb][3] = hmul2u(Q8[kb * 8 + t + 4], sc);
        }
    }

    float O[8][4];
#pragma unroll
    for (int nt = 0; nt < 8; nt++)
#pragma unroll
        for (int i = 0; i < 4; i++) O[nt][i] = 0.f;
    float m0 = -INFINITY, m1 = -INFINITY, l0 = 0.f, l1 = 0.f;

    const int ntiles = (q0 + BQ) >> 6;     // >= 2 always

    loadKV(0, 0);  cp_commit();
    loadKV(1, 64); cp_commit();

    for (int kt = 0; kt < ntiles; kt++) {
        const int k0 = kt << 6;
        asm volatile("cp.async.wait_group 1;\n" ::);   // tile kt resident
        __syncthreads();
        if (kt + 2 < ntiles) loadKV((kt + 2) % 3, (kt + 2) << 6);
        cp_commit();

        if (k0 > q0 + w * 16 + 15) continue;   // exact identity update -> skip

        const unsigned ksB = ksb + ((kt % 3) * KV_SZ) * 4;
        const unsigned vsB = vsb + ((kt % 3) * KV_SZ) * 4;

        float S[8][4];
#pragma unroll
        for (int nt = 0; nt < 8; nt++)
#pragma unroll
            for (int i = 0; i < 4; i++) S[nt][i] = 0.f;

#pragma unroll
        for (int kb = 0; kb < 4; kb++) {
            unsigned kf[8][2];
#pragma unroll
            for (int ntp = 0; ntp < 4; ntp++)
                ldsm4(kf[2*ntp][0], kf[2*ntp][1], kf[2*ntp+1][0], kf[2*ntp+1][1],
                      ksB + ((ntp * 16 + nRowF) * TS_H + kb * 8 + nKsel) * 4);
#pragma unroll
            for (int nt = 0; nt < 8; nt++)
                mma_f16(S[nt], qa[kb][0], qa[kb][1], qa[kb][2], qa[kb][3],
                        kf[nt][0], kf[nt][1]);
        }

        if (k0 + BKV - 1 > q0 + w * 16) {
#pragma unroll
            for (int nt = 0; nt < 8; nt++) {
                int col = k0 + nt * 8 + 2 * t;
                if (col > rowA)         S[nt][0] = -INFINITY;
                if (col + 1 > rowA)     S[nt][1] = -INFINITY;
                if (col > rowA + 8)     S[nt][2] = -INFINITY;
                if (col + 1 > rowA + 8) S[nt][3] = -INFINITY;
            }
        }

        float mt0 = -INFINITY, mt1 = -INFINITY;
#pragma unroll
        for (int nt = 0; nt < 8; nt++) {
            mt0 = fmaxf(mt0, fmaxf(S[nt][0], S[nt][1]));
            mt1 = fmaxf(mt1, fmaxf(S[nt][2], S[nt][3]));
        }
#pragma unroll
        for (int off = 1; off < 4; off <<= 1) {
            mt0 = fmaxf(mt0, __shfl_xor_sync(0xffffffffu, mt0, off));
            mt1 = fmaxf(mt1, __shfl_xor_sync(0xffffffffu, mt1, off));
        }
        float mn0 = fmaxf(m0, mt0), mn1 = fmaxf(m1, mt1);
        float al0 = __expf(m0 - mn0), al1 = __expf(m1 - mn1);
        m0 = mn0; m1 = mn1;

        // P in registers, laid out exactly as the PV-mma A fragments
        float ls0 = 0.f, ls1 = 0.f;
        unsigned ph[8][2];
#pragma unroll
        for (int nt = 0; nt < 8; nt++) {
            float e00 = __expf(S[nt][0] - mn0);
            float e01 = __expf(S[nt][1] - mn0);
            float e10 = __expf(S[nt][2] - mn1);
            float e11 = __expf(S[nt][3] - mn1);
            ls0 += e00 + e01;
            ls1 += e10 + e11;
            ph[nt][0] = h2u(__floats2half2_rn(e00, e01));   // row g
            ph[nt][1] = h2u(__floats2half2_rn(e10, e11));   // row g+8
        }
#pragma unroll
        for (int off = 1; off < 4; off <<= 1) {
            ls0 += __shfl_xor_sync(0xffffffffu, ls0, off);
            ls1 += __shfl_xor_sync(0xffffffffu, ls1, off);
        }
        l0 = l0 * al0 + ls0;
        l1 = l1 * al1 + ls1;
#pragma unroll
        for (int nt = 0; nt < 8; nt++) {
            O[nt][0] *= al0; O[nt][1] *= al0;
            O[nt][2] *= al1; O[nt][3] *= al1;
        }

#pragma unroll
        for (int kbv = 0; kbv < 4; kbv++) {
            unsigned vf[8][2];
#pragma unroll
            for (int ntp = 0; ntp < 4; ntp++)
                ldsm4(vf[2*ntp][0], vf[2*ntp][1], vf[2*ntp+1][0], vf[2*ntp+1][1],
                      vsB + ((ntp * 16 + nRowF) * TS_H + kbv * 8 + nKsel) * 4);
#pragma unroll
            for (int nt = 0; nt < 8; nt++)
                mma_f16(O[nt], ph[2*kbv][0], ph[2*kbv][1],
                        ph[2*kbv+1][0], ph[2*kbv+1][1],
                        vf[nt][0], vf[nt][1]);
        }
    }

    float inv0 = 1.f / l0, inv1 = 1.f / l1;
    __half* y0 = yh + (size_t)(b * SEQ + rowA) * CDIM + h * HD;
    __half* y1 = y0 + (size_t)8 * CDIM;
#pragma unroll
    for (int nt = 0; nt < 8; nt++) {
        *(unsigned*)&y0[nt * 8 + 2 * t] =
            h2u(__floats2half2_rn(O[nt][0] * inv0, O[nt][1] * inv0));
        *(unsigned*)&y1[nt * 8 + 2 * t] =
            h2u(__floats2half2_rn(O[nt][2] * inv1, O[nt][3] * inv1));
    }
}

// ---------------------------------------------------------------------------
extern "C" void kernel_launch(void* const* d_in, const int* in_sizes, int n_in,
                              void* d_out, int out_size)
{
    const float* x      = (const float*)d_in[0];
    const float* W_attn = (const float*)d_in[1];
    const float* b_attn = (const float*)d_in[2];
    const float* W_proj = (const float*)d_in[3];
    const float* b_proj = (const float*)d_in[4];
    float* out = (float*)d_out;

    __half *qkvh, *vT, *xh, *waT, *wpT, *yh;
    cudaGetSymbolAddress((void**)&qkvh, g_qkvh);
    cudaGetSymbolAddress((void**)&vT,   g_vT);
    cudaGetSymbolAddress((void**)&xh,   g_xh);
    cudaGetSymbolAddress((void**)&waT,  g_waT);
    cudaGetSymbolAddress((void**)&wpT,  g_wpT);
    cudaGetSymbolAddress((void**)&yh,   g_yh);

    cudaFuncSetAttribute(gemm_h, cudaFuncAttributeMaxDynamicSharedMemorySize,
                         GEMM_SMEM_H);
    cudaFuncSetAttribute(attn_h, cudaFuncAttributeMaxDynamicSharedMemorySize,
                         ATTN_SMEM_H);

    // 0) pre-pass
    {
        int n4x = ROWS * CDIM / 4;
        conv_half<<<(n4x + 255) / 256, 256>>>(x, xh, n4x);
        transpose_h<<<dim3(QKVC / 32, CDIM / 32), dim3(32, 8)>>>(W_attn, waT,
                                                                 CDIM, QKVC);
        transpose_h<<<dim3(CDIM / 32, CDIM / 32), dim3(32, 8)>>>(W_proj, wpT,
                                                                 CDIM, CDIM);
    }

    // 1) qkv = xh @ waT^T + b_attn -> Q|K rows (half) + V transposed (half)
    gemm_h<<<dim3(QKVC / 128, ROWS / 128), 256, GEMM_SMEM_H>>>(
        xh, waT, b_attn, nullptr, qkvh, vT, ROWS, QKVC, CDIM, 1);
    // 2) attention -> yh (half)
    attn_h<<<dim3(SEQ / BQ, NH, BATCH), 256, ATTN_SMEM_H>>>(qkvh, vT, yh);
    // 3) out = yh @ wpT^T + b_proj (fp32 out)
    gemm_h<<<dim3(CDIM / 128, ROWS / 128), 256, GEMM_SMEM_H>>>(
        yh, wpT, b_proj, out, nullptr, nullptr, ROWS, CDIM, CDIM, 0);
}